// round 14
// baseline (speedup 1.0000x reference)
#include <cuda_runtime.h>
#include <math.h>

#define N_I 60000
#define N_E 30000
#define DI  128
#define DE  64
#define HH  64
#define E_II 960000
#define E_EI 480000
#define N_TRAIN 2048
#define N_CHOSEN 1024
#define F_INTERP 0.35f
#define F_SLOPE  0.2f
#define CAP_II 64
#define CAP_EI 48
#define TII ((N_I + 63) / 64)     // 938
#define TEI ((N_E + 63) / 64)     // 469
#define SCB 192                   // scatter blocks prepended to gemm grid
#define NNVB (N_CHOSEN / 8 * 4)   // 512 virtual nn blocks
#define SMEM_FLOATS (64*66 + 64*64 + 64 + 256)    // 8640
#define SMEM_BYTES  (SMEM_FLOATS * 4)             // 34560

// ---------------- scratch (static device globals; zero-initialized at load) ----------------
// Self-cleaning invariant: every kernel_launch call leaves deg/trainflag/invch zeroed
// (done in k_post phase A after last use), so capture and each replay see identical state.
__device__ __align__(16) float g_hs_ii[N_I * HH];
__device__ __align__(16) float g_hs_ei[N_E * HH];
__device__ float g_s_ii[N_I];
__device__ float g_d_ii[N_I];
__device__ float g_d_ei[N_I];
__device__ float g_s_ei[N_E];
__device__ int   g_deg_ii[N_I];
__device__ int   g_deg_ei[N_I];
__device__ int   g_bkt_ii[(size_t)N_I * CAP_II];
__device__ int   g_bkt_ei[(size_t)N_I * CAP_EI];
__device__ __align__(16) float g_ce[N_CHOSEN * HH];
__device__ float g_sq[N_CHOSEN];
__device__ unsigned long long g_nbpack[N_CHOSEN];   // re-armed in phase A each call
__device__ int   g_trainflag[N_I];
__device__ int   g_invch[N_I];                       // j+1 encoding; 0 = not chosen
__device__ unsigned g_cnt = 0;
__device__ unsigned g_gen = 0;

// ---------------- software grid barrier (all blocks resident) ----------------
__device__ __forceinline__ void gbar() {
    __syncthreads();
    if (threadIdx.x == 0) {
        volatile unsigned* vg = &g_gen;
        unsigned my = *vg;
        __threadfence();
        if (atomicAdd(&g_cnt, 1u) == gridDim.x - 1) {
            g_cnt = 0;
            __threadfence();
            *vg = my + 1;
        } else {
            while (*vg == my) __nanosleep(64);
        }
        __threadfence();
    }
    __syncthreads();
}

// ---------------- packed f32x2 helpers (Blackwell FFMA2) ----------------
__device__ __forceinline__ unsigned long long pk2(float x) {
    unsigned long long r;
    asm("mov.b64 %0, {%1, %1};" : "=l"(r) : "f"(x));
    return r;
}
__device__ __forceinline__ void fma2(unsigned long long& d, unsigned long long a,
                                     unsigned long long b) {
    asm("fma.rn.f32x2 %0, %1, %2, %0;" : "+l"(d) : "l"(a), "l"(b));
}
__device__ __forceinline__ void upk(unsigned long long v, float& lo, float& hi) {
    asm("mov.b64 {%0, %1}, %2;" : "=f"(lo), "=f"(hi) : "l"(v));
}

// ---------------- GEMM tile (128 threads, BM=64): HS = A@W, S = HS@asrc, D = A@wd --------
// Thread (tr,tc): rows 4tr..4tr+3 x cols 8tc..8tc+7; FFMA2 packs row pairs.
__device__ void gemm_tile(const float* __restrict__ A, const float* __restrict__ W,
                          const float* __restrict__ asrc,
                          const float* __restrict__ Wdst0, const float* __restrict__ adst0,
                          const float* __restrict__ Wdst1, const float* __restrict__ adst1,
                          float* __restrict__ HS, float* __restrict__ S,
                          float* __restrict__ D0, float* __restrict__ D1,
                          int M, int K, int row0, float* sm) {
    float* As  = sm;              // [64][66] transposed (k-major), even stride
    float* Ws  = sm + 64 * 66;    // [64][64]
    float* asc = Ws + 64 * 64;    // [64]
    float* wds = asc + 64;        // [256]

    const int tid  = threadIdx.x;
    const int Mloc = M - row0;
    const int tr = tid >> 3;      // 0..15
    const int tc = tid & 7;       // 0..7

    if (Wdst0 && tid < K) {
        float s0 = 0.f, s1 = 0.f;
#pragma unroll 16
        for (int c = 0; c < HH; c++) {
            s0 += __ldg(&Wdst0[tid * HH + c]) * __ldg(&adst0[c]);
            s1 += __ldg(&Wdst1[tid * HH + c]) * __ldg(&adst1[c]);
        }
        wds[tid]       = s0;
        wds[128 + tid] = s1;
    }
    if (tid < 64) asc[tid] = asrc[tid];

    unsigned long long acc[2][8];
#pragma unroll
    for (int p = 0; p < 2; p++)
#pragma unroll
        for (int j = 0; j < 8; j++) acc[p][j] = 0ull;
    float d0 = 0.f, d1 = 0.f;

    const int nch = K >> 6;
    for (int ch = 0; ch < nch; ch++) {
        const int kk = ch << 6;
        __syncthreads();
        for (int i = tid; i < 64 * 64; i += 128) {
            int r = i >> 6, k = i & 63;
            As[k * 66 + r] = (r < Mloc) ? A[(size_t)(row0 + r) * K + kk + k] : 0.f;
        }
        for (int i = tid; i < 64 * 64; i += 128) Ws[i] = W[kk * 64 + i];
        __syncthreads();

        const float* AsB = As + tr * 4;
        const float* WsB = Ws + tc * 8;
        for (int k = 0; k < 64; k++) {
            unsigned long long a0 = *(const unsigned long long*)(AsB + k * 66);
            unsigned long long a1 = *(const unsigned long long*)(AsB + k * 66 + 2);
            float4 b0 = *(const float4*)(WsB + k * 64);
            float4 b1 = *(const float4*)(WsB + k * 64 + 4);
            unsigned long long bd[8];
            bd[0] = pk2(b0.x); bd[1] = pk2(b0.y); bd[2] = pk2(b0.z); bd[3] = pk2(b0.w);
            bd[4] = pk2(b1.x); bd[5] = pk2(b1.y); bd[6] = pk2(b1.z); bd[7] = pk2(b1.w);
#pragma unroll
            for (int j = 0; j < 8; j++) {
                fma2(acc[0][j], a0, bd[j]);
                fma2(acc[1][j], a1, bd[j]);
            }
        }
        if (Wdst0 && tid < 64 && tid < Mloc) {
            for (int k = 0; k < 64; k++) {
                float a = As[k * 66 + tid];
                d0 += a * wds[kk + k];
                d1 += a * wds[128 + kk + k];
            }
        }
    }

    float ar[8];
#pragma unroll
    for (int j = 0; j < 8; j++) ar[j] = asc[tc * 8 + j];

#pragma unroll
    for (int p = 0; p < 2; p++) {
        float lo[8], hi[8];
#pragma unroll
        for (int j = 0; j < 8; j++) upk(acc[p][j], lo[j], hi[j]);
        int rl = tr * 4 + 2 * p;
        int rh = rl + 1;
        float sl = lo[0]*ar[0]+lo[1]*ar[1]+lo[2]*ar[2]+lo[3]*ar[3]+lo[4]*ar[4]+lo[5]*ar[5]+lo[6]*ar[6]+lo[7]*ar[7];
        float sh = hi[0]*ar[0]+hi[1]*ar[1]+hi[2]*ar[2]+hi[3]*ar[3]+hi[4]*ar[4]+hi[5]*ar[5]+hi[6]*ar[6]+hi[7]*ar[7];
#pragma unroll
        for (int off = 4; off; off >>= 1) {
            sl += __shfl_down_sync(0xffffffffu, sl, off, 8);
            sh += __shfl_down_sync(0xffffffffu, sh, off, 8);
        }
        if (rl < Mloc) {
            float* dl = &HS[(size_t)(row0 + rl) * 64 + tc * 8];
            *(float4*)dl       = make_float4(lo[0], lo[1], lo[2], lo[3]);
            *(float4*)(dl + 4) = make_float4(lo[4], lo[5], lo[6], lo[7]);
            if (tc == 0) S[row0 + rl] = sl;
        }
        if (rh < Mloc) {
            float* dh = &HS[(size_t)(row0 + rh) * 64 + tc * 8];
            *(float4*)dh       = make_float4(hi[0], hi[1], hi[2], hi[3]);
            *(float4*)(dh + 4) = make_float4(hi[4], hi[5], hi[6], hi[7]);
            if (tc == 0) S[row0 + rh] = sh;
        }
    }
    if (Wdst0 && tid < 64 && tid < Mloc) {
        D0[row0 + tid] = d0;
        D1[row0 + tid] = d1;
    }
}

// ---------------- combined launch: scatter blocks [0,SCB) || GEMM blocks [SCB,..) ---------
__global__ void __launch_bounds__(128, 6)
k_gemm_all(const float* __restrict__ x_i, const float* __restrict__ Wsrc_ii,
           const float* __restrict__ asrc_ii,
           const float* __restrict__ Wdst_ii, const float* __restrict__ adst_ii,
           const float* __restrict__ Wdst_ei, const float* __restrict__ adst_ei,
           const float* __restrict__ x_e, const float* __restrict__ Wsrc_ei,
           const float* __restrict__ asrc_ei,
           const int* __restrict__ eii, const int* __restrict__ eei,
           const int* __restrict__ idxtr, const int* __restrict__ chosen) {
    extern __shared__ float sm[];
    const int bid = blockIdx.x;
    if (bid < SCB) {
        const int TOT = E_II + E_EI + N_TRAIN + N_CHOSEN;
        for (int idx = bid * 128 + threadIdx.x; idx < TOT; idx += SCB * 128) {
            if (idx < E_II) {
                int d = eii[E_II + idx];
                int pos = atomicAdd(&g_deg_ii[d], 1);
                if (pos < CAP_II) g_bkt_ii[(size_t)d * CAP_II + pos] = eii[idx];
            } else if (idx < E_II + E_EI) {
                int e2 = idx - E_II;
                int d = eei[E_EI + e2];
                int pos = atomicAdd(&g_deg_ei[d], 1);
                if (pos < CAP_EI) g_bkt_ei[(size_t)d * CAP_EI + pos] = eei[e2];
            } else if (idx < E_II + E_EI + N_TRAIN) {
                g_trainflag[idxtr[idx - E_II - E_EI]] = 1;
            } else {
                int j = idx - E_II - E_EI - N_TRAIN;
                g_invch[chosen[j]] = j + 1;       // 0 = not chosen
            }
        }
        return;
    }
    int t = bid - SCB;
    if (t < TII)
        gemm_tile(x_i, Wsrc_ii, asrc_ii, Wdst_ii, adst_ii, Wdst_ei, adst_ei,
                  g_hs_ii, g_s_ii, g_d_ii, g_d_ei, N_I, 128, t * 64, sm);
    else
        gemm_tile(x_e, Wsrc_ei, asrc_ei, nullptr, nullptr, nullptr, nullptr,
                  g_hs_ei, g_s_ei, nullptr, nullptr, N_E, 64, (t - TII) * 64, sm);
}

// ---------------- per-graph gather: 2 edges/step, half-warp float4 rows ----------------
__device__ __forceinline__ float4 aggr_one(const int* __restrict__ bkt, int deg,
                                           const float* __restrict__ S, float dval,
                                           const float* __restrict__ HS,
                                           int lane, int half, int qlane) {
    float4 v = make_float4(0.f, 0.f, 0.f, 0.f);
    float esum = 0.f;
    for (int base = 0; base < deg; base += 32) {
        int j = base + lane;
        int sidx = 0;
        float e = 0.f;
        if (j < deg) {
            sidx = bkt[j];
            float a = __ldg(&S[sidx]) + dval;
            a = a > 0.f ? a : F_SLOPE * a;
            e = expf(a);
        }
        int cnt = min(32, deg - base);
        int steps = (cnt + 1) >> 1;
#pragma unroll 8
        for (int t = 0; t < steps; t++) {
            int sl = 2 * t + half;             // out-of-range edges have e=0, sidx=0
            float et = __shfl_sync(0xffffffffu, e, sl);
            int   st = __shfl_sync(0xffffffffu, sidx, sl);
            float4 h = *(const float4*)&HS[(size_t)st * 64 + qlane * 4];
            v.x += et * h.x; v.y += et * h.y; v.z += et * h.z; v.w += et * h.w;
        }
        esum += e;
    }
#pragma unroll
    for (int off = 16; off; off >>= 1)
        esum += __shfl_xor_sync(0xffffffffu, esum, off);
    if (esum > 0.f) {
        float inv = 1.f / esum;
        v.x *= inv; v.y *= inv; v.z *= inv; v.w *= inv;
    }
    return v;
}

// ---------------- persistent post kernel: aggr+classifier | NN | synth ----------------
__global__ void __launch_bounds__(256)
k_post(const float* __restrict__ b_ii, const float* __restrict__ b_ei,
       const float* __restrict__ linW, const float* __restrict__ linb,
       const float* __restrict__ rn, const int* __restrict__ labels,
       const int* __restrict__ chosen,
       float* __restrict__ out, int probN, int writeExtras) {
    __shared__ float tile[64 * 65];
    __shared__ float sqj[64];
    __shared__ float cei[8 * 64];
    const int tid = threadIdx.x;
    const int bid = blockIdx.x;
    const int G   = gridDim.x;
    const int wid = tid >> 5, lane = tid & 31;

    // ===== Phase A: aggregation + bias + relu + classifier + extras =====
    for (int i = bid * 256 + tid; i < N_CHOSEN; i += G * 256)
        g_nbpack[i] = 0xFFFFFFFFFFFFFFFFull;

    const int half = lane >> 4, qlane = lane & 15;
    for (int dst = bid * 8 + wid; dst < N_I; dst += G * 8) {
        float4 v0 = aggr_one(&g_bkt_ii[(size_t)dst * CAP_II], min(g_deg_ii[dst], CAP_II),
                             g_s_ii, g_d_ii[dst], g_hs_ii, lane, half, qlane);
        float4 v1 = aggr_one(&g_bkt_ei[(size_t)dst * CAP_EI], min(g_deg_ei[dst], CAP_EI),
                             g_s_ei, g_d_ei[dst], g_hs_ei, lane, half, qlane);
        float4 v;
        v.x = v0.x + v1.x; v.y = v0.y + v1.y; v.z = v0.z + v1.z; v.w = v0.w + v1.w;
        v.x += __shfl_xor_sync(0xffffffffu, v.x, 16);
        v.y += __shfl_xor_sync(0xffffffffu, v.y, 16);
        v.z += __shfl_xor_sync(0xffffffffu, v.z, 16);
        v.w += __shfl_xor_sync(0xffffffffu, v.w, 16);

        float4 bi = *(const float4*)&b_ii[qlane * 4];
        float4 be = *(const float4*)&b_ei[qlane * 4];
        float4 o;
        o.x = 0.5f * (v.x + bi.x + be.x); o.x = o.x > 0.f ? o.x : 0.f;
        o.y = 0.5f * (v.y + bi.y + be.y); o.y = o.y > 0.f ? o.y : 0.f;
        o.z = 0.5f * (v.z + bi.z + be.z); o.z = o.z > 0.f ? o.z : 0.f;
        o.w = 0.5f * (v.w + bi.w + be.w); o.w = o.w > 0.f ? o.w : 0.f;

        int ic = g_invch[dst];
        if (ic > 0) {
            int icc = ic - 1;
            if (half == 0)
                *(float4*)&g_ce[(size_t)icc * 64 + qlane * 4] = o;
            float sq = o.x * o.x + o.y * o.y + o.z * o.z + o.w * o.w;
#pragma unroll
            for (int off = 8; off; off >>= 1)
                sq += __shfl_xor_sync(0xffffffffu, sq, off);
            if (lane == 0) g_sq[icc] = sq;
        }

        int base = qlane * 4;
        float l0 = o.x * __ldg(&linW[base * 2])     + o.y * __ldg(&linW[base * 2 + 2]) +
                   o.z * __ldg(&linW[base * 2 + 4]) + o.w * __ldg(&linW[base * 2 + 6]);
        float l1 = o.x * __ldg(&linW[base * 2 + 1]) + o.y * __ldg(&linW[base * 2 + 3]) +
                   o.z * __ldg(&linW[base * 2 + 5]) + o.w * __ldg(&linW[base * 2 + 7]);
#pragma unroll
        for (int off = 8; off; off >>= 1) {
            l0 += __shfl_xor_sync(0xffffffffu, l0, off);
            l1 += __shfl_xor_sync(0xffffffffu, l1, off);
        }
        if (lane == 0) {
            l0 += __ldg(&linb[0]);
            l1 += __ldg(&linb[1]);
            float m = fmaxf(l0, l1);
            float e0 = expf(l0 - m), e1 = expf(l1 - m);
            float inv = 1.f / (e0 + e1);
            out[dst * 2]     = e0 * inv;
            out[dst * 2 + 1] = e1 * inv;
            if (writeExtras) {
                int moff = probN * 2;
                out[moff + dst]             = g_trainflag[dst] ? 1.f : 0.f;
                out[moff + probN + dst]     = (float)labels[dst];
                out[moff + 2 * probN + dst] = rn[dst];
            }
        }
        if (lane == 0)      g_trainflag[dst] = 0;
        else if (lane == 1) g_invch[dst] = 0;
        else if (lane == 2) g_deg_ii[dst] = 0;
        else if (lane == 3) g_deg_ei[dst] = 0;
    }
    gbar();

    // ===== Phase B: NN (512 virtual blocks) =====
    for (int vb = bid; vb < NNVB; vb += G) {
        int i = (vb >> 2) * 8 + wid;
        int jbase = (vb & 3) * 256;

        __syncthreads();
        cei[wid * 64 + lane]      = g_ce[i * 64 + lane];
        cei[wid * 64 + 32 + lane] = g_ce[i * 64 + 32 + lane];
        const float sqi = g_sq[i];
        float best = 3.4e38f;
        int bestj = 0x7fffffff;

        for (int tb = jbase; tb < jbase + 256; tb += 64) {
            __syncthreads();
            for (int idx = tid; idx < 64 * 64; idx += 256) {
                int j = idx >> 6, k = idx & 63;
                tile[j * 65 + k] = g_ce[(tb + j) * 64 + k];
            }
            if (tid < 64) sqj[tid] = g_sq[tb + tid];
            __syncthreads();

#pragma unroll
            for (int hh = 0; hh < 2; hh++) {
                int jl = lane + hh * 32;
                int j = tb + jl;
                if (j == i) continue;
                float dot = 0.f;
#pragma unroll 16
                for (int k = 0; k < 64; k++) dot += cei[wid * 64 + k] * tile[jl * 65 + k];
                float d2 = sqi + sqj[jl] - 2.f * dot;
                d2 = d2 > 0.f ? d2 : 0.f;
                if (d2 < best || (d2 == best && j < bestj)) { best = d2; bestj = j; }
            }
        }
#pragma unroll
        for (int off = 16; off; off >>= 1) {
            float ob = __shfl_down_sync(0xffffffffu, best, off);
            int   oj = __shfl_down_sync(0xffffffffu, bestj, off);
            if (ob < best || (ob == best && oj < bestj)) { best = ob; bestj = oj; }
        }
        if (lane == 0) {
            unsigned long long pk = ((unsigned long long)__float_as_uint(best) << 32) |
                                    (unsigned)bestj;
            atomicMin(&g_nbpack[i], pk);
        }
    }
    gbar();

    // ===== Phase C: synthetic SMOTE rows =====
    for (int i = bid * 8 + wid; i < N_CHOSEN; i += G * 8) {
        int nbi = (int)(g_nbpack[i] & 0xFFFFFFFFull);
        float c0 = g_ce[i * 64 + lane],   c1 = g_ce[i * 64 + 32 + lane];
        float n0 = g_ce[nbi * 64 + lane], n1 = g_ce[nbi * 64 + 32 + lane];
        float v0 = c0 + (n0 - c0) * F_INTERP;
        float v1 = c1 + (n1 - c1) * F_INTERP;
        float l0 = v0 * __ldg(&linW[lane * 2])     + v1 * __ldg(&linW[(lane + 32) * 2]);
        float l1 = v0 * __ldg(&linW[lane * 2 + 1]) + v1 * __ldg(&linW[(lane + 32) * 2 + 1]);
#pragma unroll
        for (int off = 16; off; off >>= 1) {
            l0 += __shfl_down_sync(0xffffffffu, l0, off);
            l1 += __shfl_down_sync(0xffffffffu, l1, off);
        }
        if (lane == 0) {
            int n = N_I + i;
            l0 += __ldg(&linb[0]);
            l1 += __ldg(&linb[1]);
            float m = fmaxf(l0, l1);
            float e0 = expf(l0 - m), e1 = expf(l1 - m);
            float inv = 1.f / (e0 + e1);
            out[n * 2]     = e0 * inv;
            out[n * 2 + 1] = e1 * inv;
            if (writeExtras) {
                int moff = probN * 2;
                out[moff + n]             = 1.f;
                out[moff + probN + n]     = 1.f;
                float rc = rn[chosen[i]];
                out[moff + 2 * probN + n] = rc + (rn[chosen[nbi]] - rc) * F_INTERP;
            }
        }
    }
}

// ---------------- launch ----------------
extern "C" void kernel_launch(void* const* d_in, const int* in_sizes, int n_in,
                              void* d_out, int out_size) {
    const float* x_i     = (const float*)d_in[0];
    const float* x_e     = (const float*)d_in[1];
    const float* Wsrc_ii = (const float*)d_in[2];
    const float* Wdst_ii = (const float*)d_in[3];
    const float* asrc_ii = (const float*)d_in[4];
    const float* adst_ii = (const float*)d_in[5];
    const float* b_ii    = (const float*)d_in[6];
    // d_in[7..11]: ie branch — unused downstream in the reference; skipped.
    const float* Wsrc_ei = (const float*)d_in[12];
    const float* Wdst_ei = (const float*)d_in[13];
    const float* asrc_ei = (const float*)d_in[14];
    const float* adst_ei = (const float*)d_in[15];
    const float* b_ei    = (const float*)d_in[16];
    const float* linW    = (const float*)d_in[17];
    const float* linb    = (const float*)d_in[18];
    const float* rn      = (const float*)d_in[19];
    const int*   eii     = (const int*)d_in[20];
    const int*   eei     = (const int*)d_in[22];
    const int*   labels  = (const int*)d_in[23];
    const int*   idxtr   = (const int*)d_in[24];
    const int*   chosen  = (const int*)d_in[25];
    float* out = (float*)d_out;

    cudaFuncSetAttribute(k_gemm_all, cudaFuncAttributeMaxDynamicSharedMemorySize, SMEM_BYTES);
    k_gemm_all<<<SCB + TII + TEI, 128, SMEM_BYTES>>>(
        x_i, Wsrc_ii, asrc_ii, Wdst_ii, adst_ii, Wdst_ei, adst_ei,
        x_e, Wsrc_ei, asrc_ei, eii, eei, idxtr, chosen);

    int sms = 0, nb = 0;
    cudaDeviceGetAttribute(&sms, cudaDevAttrMultiProcessorCount, 0);
    cudaOccupancyMaxActiveBlocksPerMultiprocessor(&nb, k_post, 256, 0);
    if (nb < 1) nb = 1;
    int G = nb * sms;

    int probN = N_I + N_CHOSEN;
    int writeExtras = (out_size >= probN * 5) ? 1 : 0;
    k_post<<<G, 256>>>(b_ii, b_ei, linW, linb, rn, labels, chosen,
                       out, probN, writeExtras);
}

// round 15
// speedup vs baseline: 1.3125x; 1.3125x over previous
#include <cuda_runtime.h>
#include <math.h>

#define N_I 60000
#define N_E 30000
#define DI  128
#define DE  64
#define HH  64
#define E_II 960000
#define E_EI 480000
#define N_TRAIN 2048
#define N_CHOSEN 1024
#define F_INTERP 0.35f
#define F_SLOPE  0.2f
#define CAP_II 64
#define CAP_EI 48
#define TII ((N_I + 127) / 128)   // 469
#define TEI ((N_E + 127) / 128)   // 235
#define SCB 128                   // scatter blocks prepended to gemm grid
#define NNB ((N_CHOSEN / 8) * 4)  // 512 nn blocks
#define SMEM_FLOATS (64*132 + 64*64 + 64 + 256)   // 12864
#define SMEM_BYTES  (SMEM_FLOATS * 4)             // 51456

// ---------------- scratch (static device globals; zero-initialized at load) ----------------
// Self-cleaning invariant: every kernel_launch call leaves deg/trainflag/invch zeroed
// (done by k_aggr after last use), so capture and each replay see identical state.
__device__ __align__(16) float g_hs_ii[N_I * HH];
__device__ __align__(16) float g_hs_ei[N_E * HH];
__device__ float g_s_ii[N_I];
__device__ float g_d_ii[N_I];
__device__ float g_d_ei[N_I];
__device__ float g_s_ei[N_E];
__device__ int   g_deg_ii[N_I];
__device__ int   g_deg_ei[N_I];
__device__ int   g_bkt_ii[(size_t)N_I * CAP_II];
__device__ int   g_bkt_ei[(size_t)N_I * CAP_EI];
__device__ __align__(16) float g_ce[N_CHOSEN * HH];
__device__ float g_sq[N_CHOSEN];
__device__ unsigned long long g_nbpack[N_CHOSEN];   // re-armed in k_aggr each call
__device__ int   g_trainflag[N_I];
__device__ int   g_invch[N_I];                       // j+1 encoding; 0 = not chosen

// ---------------- packed f32x2 helpers (Blackwell FFMA2) ----------------
__device__ __forceinline__ unsigned long long pk2(float x) {
    unsigned long long r;
    asm("mov.b64 %0, {%1, %1};" : "=l"(r) : "f"(x));
    return r;
}
__device__ __forceinline__ void fma2(unsigned long long& d, unsigned long long a,
                                     unsigned long long b) {
    asm("fma.rn.f32x2 %0, %1, %2, %0;" : "+l"(d) : "l"(a), "l"(b));
}
__device__ __forceinline__ void upk(unsigned long long v, float& lo, float& hi) {
    asm("mov.b64 {%0, %1}, %2;" : "=f"(lo), "=f"(hi) : "l"(v));
}

// ---------------- GEMM tile (256 threads, BM=128): HS = A@W, S = HS@asrc, D = A@wd ------
// Thread (tr,tc): 4 contiguous rows 4tr..4tr+3 x 8 cols 8tc..8tc+7.
// FFMA2 packs COLUMN pairs: B pairs come packed straight from LDS.128 (zero movs);
// only the 4 A row values need duplication (4 pk2 movs/k vs 8 before).
__device__ void gemm_tile(const float* __restrict__ A, const float* __restrict__ W,
                          const float* __restrict__ asrc,
                          const float* __restrict__ Wdst0, const float* __restrict__ adst0,
                          const float* __restrict__ Wdst1, const float* __restrict__ adst1,
                          float* __restrict__ HS, float* __restrict__ S,
                          float* __restrict__ D0, float* __restrict__ D1,
                          int M, int K, int row0, float* sm) {
    float* As  = sm;              // [64][132] transposed; 132 keeps 16B alignment per k-row
    float* Ws  = sm + 64 * 132;   // [64][64]
    float* asc = Ws + 64 * 64;    // [64]
    float* wds = asc + 64;        // [256]

    const int tid  = threadIdx.x;
    const int Mloc = M - row0;
    const int tr = tid >> 3;      // 0..31
    const int tc = tid & 7;       // 0..7

    if (Wdst0 && tid < K) {
        float s0 = 0.f, s1 = 0.f;
#pragma unroll 16
        for (int c = 0; c < HH; c++) {
            s0 += __ldg(&Wdst0[tid * HH + c]) * __ldg(&adst0[c]);
            s1 += __ldg(&Wdst1[tid * HH + c]) * __ldg(&adst1[c]);
        }
        wds[tid]       = s0;
        wds[128 + tid] = s1;
    }
    if (tid < 64) asc[tid] = asrc[tid];

    unsigned long long acc[4][4];
#pragma unroll
    for (int r = 0; r < 4; r++)
#pragma unroll
        for (int p = 0; p < 4; p++) acc[r][p] = 0ull;
    float d0 = 0.f, d1 = 0.f;

    const int nch = K >> 6;
    for (int ch = 0; ch < nch; ch++) {
        const int kk = ch << 6;
        __syncthreads();
        for (int i = tid; i < 128 * 64; i += 256) {
            int r = i >> 6, k = i & 63;
            As[k * 132 + r] = (r < Mloc) ? A[(size_t)(row0 + r) * K + kk + k] : 0.f;
        }
        for (int i = tid; i < 64 * 64; i += 256) Ws[i] = W[kk * 64 + i];
        __syncthreads();

        const float* AsB = As + tr * 4;
        const float* WsB = Ws + tc * 8;
        for (int k = 0; k < 64; k++) {
            float4 a4 = *(const float4*)(AsB + k * 132);
            ulonglong2 bA = *(const ulonglong2*)(WsB + k * 64);      // col pairs {0,1},{2,3}
            ulonglong2 bB = *(const ulonglong2*)(WsB + k * 64 + 4);  // col pairs {4,5},{6,7}
            unsigned long long ad[4];
            ad[0] = pk2(a4.x); ad[1] = pk2(a4.y); ad[2] = pk2(a4.z); ad[3] = pk2(a4.w);
#pragma unroll
            for (int r = 0; r < 4; r++) {
                fma2(acc[r][0], ad[r], bA.x);
                fma2(acc[r][1], ad[r], bA.y);
                fma2(acc[r][2], ad[r], bB.x);
                fma2(acc[r][3], ad[r], bB.y);
            }
        }
        if (Wdst0 && tid < 128 && tid < Mloc) {
            for (int k = 0; k < 64; k++) {
                float a = As[k * 132 + tid];
                d0 += a * wds[kk + k];
                d1 += a * wds[128 + kk + k];
            }
        }
    }

    float ar[8];
#pragma unroll
    for (int j = 0; j < 8; j++) ar[j] = asc[tc * 8 + j];

#pragma unroll
    for (int r = 0; r < 4; r++) {
        float c[8];
        upk(acc[r][0], c[0], c[1]);
        upk(acc[r][1], c[2], c[3]);
        upk(acc[r][2], c[4], c[5]);
        upk(acc[r][3], c[6], c[7]);
        int row = tr * 4 + r;
        float s = c[0]*ar[0]+c[1]*ar[1]+c[2]*ar[2]+c[3]*ar[3]+
                  c[4]*ar[4]+c[5]*ar[5]+c[6]*ar[6]+c[7]*ar[7];
#pragma unroll
        for (int off = 4; off; off >>= 1)
            s += __shfl_down_sync(0xffffffffu, s, off, 8);
        if (row < Mloc) {
            float* dl = &HS[(size_t)(row0 + row) * 64 + tc * 8];
            *(float4*)dl       = make_float4(c[0], c[1], c[2], c[3]);
            *(float4*)(dl + 4) = make_float4(c[4], c[5], c[6], c[7]);
            if (tc == 0) S[row0 + row] = s;
        }
    }
    if (Wdst0 && tid < 128 && tid < Mloc) {
        D0[row0 + tid] = d0;
        D1[row0 + tid] = d1;
    }
}

// ---------------- combined launch: scatter blocks [0,SCB) || GEMM blocks [SCB,..) ---------
__global__ void __launch_bounds__(256, 3)
k_gemm_all(const float* __restrict__ x_i, const float* __restrict__ Wsrc_ii,
           const float* __restrict__ asrc_ii,
           const float* __restrict__ Wdst_ii, const float* __restrict__ adst_ii,
           const float* __restrict__ Wdst_ei, const float* __restrict__ adst_ei,
           const float* __restrict__ x_e, const float* __restrict__ Wsrc_ei,
           const float* __restrict__ asrc_ei,
           const int* __restrict__ eii, const int* __restrict__ eei,
           const int* __restrict__ idxtr, const int* __restrict__ chosen) {
    extern __shared__ float sm[];
    const int bid = blockIdx.x;
    if (bid < SCB) {
        const int TOT = E_II + E_EI + N_TRAIN + N_CHOSEN;
        for (int idx = bid * 256 + threadIdx.x; idx < TOT; idx += SCB * 256) {
            if (idx < E_II) {
                int d = eii[E_II + idx];
                int pos = atomicAdd(&g_deg_ii[d], 1);
                if (pos < CAP_II) g_bkt_ii[(size_t)d * CAP_II + pos] = eii[idx];
            } else if (idx < E_II + E_EI) {
                int e2 = idx - E_II;
                int d = eei[E_EI + e2];
                int pos = atomicAdd(&g_deg_ei[d], 1);
                if (pos < CAP_EI) g_bkt_ei[(size_t)d * CAP_EI + pos] = eei[e2];
            } else if (idx < E_II + E_EI + N_TRAIN) {
                g_trainflag[idxtr[idx - E_II - E_EI]] = 1;
            } else {
                int j = idx - E_II - E_EI - N_TRAIN;
                g_invch[chosen[j]] = j + 1;       // 0 = not chosen
            }
        }
        return;
    }
    int t = bid - SCB;
    if (t < TII)
        gemm_tile(x_i, Wsrc_ii, asrc_ii, Wdst_ii, adst_ii, Wdst_ei, adst_ei,
                  g_hs_ii, g_s_ii, g_d_ii, g_d_ei, N_I, 128, t * 128, sm);
    else
        gemm_tile(x_e, Wsrc_ei, asrc_ei, nullptr, nullptr, nullptr, nullptr,
                  g_hs_ei, g_s_ei, nullptr, nullptr, N_E, 64, (t - TII) * 128, sm);
}

// ---------------- per-graph gather: 2 edges/step, half-warp float4 rows ----------------
__device__ __forceinline__ float4 aggr_one(const int* __restrict__ bkt, int deg,
                                           const float* __restrict__ S, float dval,
                                           const float* __restrict__ HS,
                                           int lane, int half, int qlane) {
    float4 v = make_float4(0.f, 0.f, 0.f, 0.f);
    float esum = 0.f;
    for (int base = 0; base < deg; base += 32) {
        int j = base + lane;
        int sidx = 0;
        float e = 0.f;
        if (j < deg) {
            sidx = bkt[j];
            float a = __ldg(&S[sidx]) + dval;
            a = a > 0.f ? a : F_SLOPE * a;
            e = expf(a);
        }
        int cnt = min(32, deg - base);
        int steps = (cnt + 1) >> 1;
#pragma unroll 8
        for (int t = 0; t < steps; t++) {
            int sl = 2 * t + half;             // out-of-range edges have e=0, sidx=0
            float et = __shfl_sync(0xffffffffu, e, sl);
            int   st = __shfl_sync(0xffffffffu, sidx, sl);
            float4 h = *(const float4*)&HS[(size_t)st * 64 + qlane * 4];
            v.x += et * h.x; v.y += et * h.y; v.z += et * h.z; v.w += et * h.w;
        }
        esum += e;
    }
#pragma unroll
    for (int off = 16; off; off >>= 1)
        esum += __shfl_xor_sync(0xffffffffu, esum, off);
    if (esum > 0.f) {
        float inv = 1.f / esum;
        v.x *= inv; v.y *= inv; v.z *= inv; v.w *= inv;
    }
    return v;
}

// ---------------- fused: aggregation + bias + relu + CLASSIFIER + extras ----------------
__global__ void k_aggr(const float* __restrict__ b_ii, const float* __restrict__ b_ei,
                       const float* __restrict__ linW, const float* __restrict__ linb,
                       const float* __restrict__ rn, const int* __restrict__ labels,
                       float* __restrict__ out, int probN, int writeExtras) {
    int gtid = blockIdx.x * blockDim.x + threadIdx.x;
    if (gtid < N_CHOSEN) g_nbpack[gtid] = 0xFFFFFFFFFFFFFFFFull;  // before k_nn runs

    int dst = blockIdx.x * (blockDim.x >> 5) + (threadIdx.x >> 5);
    int lane = threadIdx.x & 31;
    int half = lane >> 4, qlane = lane & 15;
    if (dst >= N_I) return;

    float4 v0 = aggr_one(&g_bkt_ii[(size_t)dst * CAP_II], min(g_deg_ii[dst], CAP_II),
                         g_s_ii, g_d_ii[dst], g_hs_ii, lane, half, qlane);
    float4 v1 = aggr_one(&g_bkt_ei[(size_t)dst * CAP_EI], min(g_deg_ei[dst], CAP_EI),
                         g_s_ei, g_d_ei[dst], g_hs_ei, lane, half, qlane);
    float4 v;
    v.x = v0.x + v1.x; v.y = v0.y + v1.y; v.z = v0.z + v1.z; v.w = v0.w + v1.w;
    v.x += __shfl_xor_sync(0xffffffffu, v.x, 16);
    v.y += __shfl_xor_sync(0xffffffffu, v.y, 16);
    v.z += __shfl_xor_sync(0xffffffffu, v.z, 16);
    v.w += __shfl_xor_sync(0xffffffffu, v.w, 16);

    float4 bi = *(const float4*)&b_ii[qlane * 4];
    float4 be = *(const float4*)&b_ei[qlane * 4];
    float4 o;
    o.x = 0.5f * (v.x + bi.x + be.x); o.x = o.x > 0.f ? o.x : 0.f;
    o.y = 0.5f * (v.y + bi.y + be.y); o.y = o.y > 0.f ? o.y : 0.f;
    o.z = 0.5f * (v.z + bi.z + be.z); o.z = o.z > 0.f ? o.z : 0.f;
    o.w = 0.5f * (v.w + bi.w + be.w); o.w = o.w > 0.f ? o.w : 0.f;

    int ic = g_invch[dst];
    if (ic > 0) {
        int icc = ic - 1;
        if (half == 0)
            *(float4*)&g_ce[(size_t)icc * 64 + qlane * 4] = o;
        float sq = o.x * o.x + o.y * o.y + o.z * o.z + o.w * o.w;
#pragma unroll
        for (int off = 8; off; off >>= 1)
            sq += __shfl_xor_sync(0xffffffffu, sq, off);
        if (lane == 0) g_sq[icc] = sq;
    }

    int base = qlane * 4;
    float l0 = o.x * __ldg(&linW[base * 2])     + o.y * __ldg(&linW[base * 2 + 2]) +
               o.z * __ldg(&linW[base * 2 + 4]) + o.w * __ldg(&linW[base * 2 + 6]);
    float l1 = o.x * __ldg(&linW[base * 2 + 1]) + o.y * __ldg(&linW[base * 2 + 3]) +
               o.z * __ldg(&linW[base * 2 + 5]) + o.w * __ldg(&linW[base * 2 + 7]);
#pragma unroll
    for (int off = 8; off; off >>= 1) {
        l0 += __shfl_xor_sync(0xffffffffu, l0, off);
        l1 += __shfl_xor_sync(0xffffffffu, l1, off);
    }
    if (lane == 0) {
        l0 += __ldg(&linb[0]);
        l1 += __ldg(&linb[1]);
        float m = fmaxf(l0, l1);
        float e0 = expf(l0 - m), e1 = expf(l1 - m);
        float inv = 1.f / (e0 + e1);
        out[dst * 2]     = e0 * inv;
        out[dst * 2 + 1] = e1 * inv;
        if (writeExtras) {
            int moff = probN * 2;
            out[moff + dst]             = g_trainflag[dst] ? 1.f : 0.f;
            out[moff + probN + dst]     = (float)labels[dst];
            out[moff + 2 * probN + dst] = rn[dst];
        }
    }
    if (lane == 0)      g_trainflag[dst] = 0;
    else if (lane == 1) g_invch[dst] = 0;
    else if (lane == 2) g_deg_ii[dst] = 0;
    else if (lane == 3) g_deg_ei[dst] = 0;
}

// ---------------- NN: block = 8 i's x 256-j chunk; packed atomicMin merge ----------------
__global__ void k_nn(int dummy) {
    __shared__ float tile[64 * 65];
    __shared__ float sqj[64];
    __shared__ float cei[8 * 64];
    const int tid = threadIdx.x;
    const int wid = tid >> 5, lane = tid & 31;
    int i = (blockIdx.x >> 2) * 8 + wid;
    int jbase = (blockIdx.x & 3) * 256;

    cei[wid * 64 + lane]      = g_ce[i * 64 + lane];
    cei[wid * 64 + 32 + lane] = g_ce[i * 64 + 32 + lane];
    const float sqi = g_sq[i];
    float best = 3.4e38f;
    int bestj = 0x7fffffff;

    for (int tb = jbase; tb < jbase + 256; tb += 64) {
        __syncthreads();
        for (int idx = tid; idx < 64 * 64; idx += 256) {
            int j = idx >> 6, k = idx & 63;
            tile[j * 65 + k] = g_ce[(tb + j) * 64 + k];
        }
        if (tid < 64) sqj[tid] = g_sq[tb + tid];
        __syncthreads();

#pragma unroll
        for (int hh = 0; hh < 2; hh++) {
            int jl = lane + hh * 32;
            int j = tb + jl;
            if (j == i) continue;
            float dot = 0.f;
#pragma unroll 16
            for (int k = 0; k < 64; k++) dot += cei[wid * 64 + k] * tile[jl * 65 + k];
            float d2 = sqi + sqj[jl] - 2.f * dot;
            d2 = d2 > 0.f ? d2 : 0.f;
            if (d2 < best || (d2 == best && j < bestj)) { best = d2; bestj = j; }
        }
    }
#pragma unroll
    for (int off = 16; off; off >>= 1) {
        float ob = __shfl_down_sync(0xffffffffu, best, off);
        int   oj = __shfl_down_sync(0xffffffffu, bestj, off);
        if (ob < best || (ob == best && oj < bestj)) { best = ob; bestj = oj; }
    }
    if (lane == 0) {
        unsigned long long pk = ((unsigned long long)__float_as_uint(best) << 32) |
                                (unsigned)bestj;
        atomicMin(&g_nbpack[i], pk);
    }
}

// ---------------- synthetic SMOTE rows: probs + extras ----------------
__global__ void k_synth(const float* __restrict__ linW, const float* __restrict__ linb,
                        const float* __restrict__ rn, const int* __restrict__ chosen,
                        float* __restrict__ out, int probN, int writeExtras) {
    int i = blockIdx.x * (blockDim.x >> 5) + (threadIdx.x >> 5);
    int lane = threadIdx.x & 31;
    if (i >= N_CHOSEN) return;
    int nbi = (int)(g_nbpack[i] & 0xFFFFFFFFull);
    float c0 = g_ce[i * 64 + lane],   c1 = g_ce[i * 64 + 32 + lane];
    float n0 = g_ce[nbi * 64 + lane], n1 = g_ce[nbi * 64 + 32 + lane];
    float v0 = c0 + (n0 - c0) * F_INTERP;
    float v1 = c1 + (n1 - c1) * F_INTERP;
    float l0 = v0 * __ldg(&linW[lane * 2])     + v1 * __ldg(&linW[(lane + 32) * 2]);
    float l1 = v0 * __ldg(&linW[lane * 2 + 1]) + v1 * __ldg(&linW[(lane + 32) * 2 + 1]);
#pragma unroll
    for (int off = 16; off; off >>= 1) {
        l0 += __shfl_down_sync(0xffffffffu, l0, off);
        l1 += __shfl_down_sync(0xffffffffu, l1, off);
    }
    if (lane == 0) {
        int n = N_I + i;
        l0 += __ldg(&linb[0]);
        l1 += __ldg(&linb[1]);
        float m = fmaxf(l0, l1);
        float e0 = expf(l0 - m), e1 = expf(l1 - m);
        float inv = 1.f / (e0 + e1);
        out[n * 2]     = e0 * inv;
        out[n * 2 + 1] = e1 * inv;
        if (writeExtras) {
            int moff = probN * 2;
            out[moff + n]             = 1.f;
            out[moff + probN + n]     = 1.f;
            float rc = rn[chosen[i]];
            out[moff + 2 * probN + n] = rc + (rn[chosen[nbi]] - rc) * F_INTERP;
        }
    }
}

// ---------------- launch ----------------
extern "C" void kernel_launch(void* const* d_in, const int* in_sizes, int n_in,
                              void* d_out, int out_size) {
    const float* x_i     = (const float*)d_in[0];
    const float* x_e     = (const float*)d_in[1];
    const float* Wsrc_ii = (const float*)d_in[2];
    const float* Wdst_ii = (const float*)d_in[3];
    const float* asrc_ii = (const float*)d_in[4];
    const float* adst_ii = (const float*)d_in[5];
    const float* b_ii    = (const float*)d_in[6];
    // d_in[7..11]: ie branch — unused downstream in the reference; skipped.
    const float* Wsrc_ei = (const float*)d_in[12];
    const float* Wdst_ei = (const float*)d_in[13];
    const float* asrc_ei = (const float*)d_in[14];
    const float* adst_ei = (const float*)d_in[15];
    const float* b_ei    = (const float*)d_in[16];
    const float* linW    = (const float*)d_in[17];
    const float* linb    = (const float*)d_in[18];
    const float* rn      = (const float*)d_in[19];
    const int*   eii     = (const int*)d_in[20];
    const int*   eei     = (const int*)d_in[22];
    const int*   labels  = (const int*)d_in[23];
    const int*   idxtr   = (const int*)d_in[24];
    const int*   chosen  = (const int*)d_in[25];
    float* out = (float*)d_out;

    cudaFuncSetAttribute(k_gemm_all, cudaFuncAttributeMaxDynamicSharedMemorySize, SMEM_BYTES);
    k_gemm_all<<<SCB + TII + TEI, 256, SMEM_BYTES>>>(
        x_i, Wsrc_ii, asrc_ii, Wdst_ii, adst_ii, Wdst_ei, adst_ei,
        x_e, Wsrc_ei, asrc_ei, eii, eei, idxtr, chosen);

    int probN = N_I + N_CHOSEN;
    int writeExtras = (out_size >= probN * 5) ? 1 : 0;

    k_aggr<<<(N_I + 7) / 8, 256>>>(b_ii, b_ei, linW, linb, rn, labels,
                                   out, probN, writeExtras);

    k_nn<<<NNB, 256>>>(0);

    k_synth<<<(N_CHOSEN + 7) / 8, 256>>>(linW, linb, rn, chosen, out, probN, writeExtras);
}